// round 10
// baseline (speedup 1.0000x reference)
#include <cuda_runtime.h>

// DeltaSynapse: I[b,o] = sum_e Weff[b,e,o] * sum_d (Xd[d,b,e]*(Wshort[d,b,e]+1)) * delaymap[d,e,o]
// Weff[b,e,o] = sg[e,o]*(W[e,o]*(1-frac[e,o]) + Wlong[b,e,o]*frac[e,o])
//
// D=8, B=16, N=2048. HBM-bound (~417 MB unique).
// R7 (WIN 79.9us): 148 CTAs (1/SM, 1 wave), 512 thr, float2/thread, 4KB runs.
// R8 (neutral): finer tiles / 2 waves -> reverted.
// R9: register-free lookahead — prefetch.global.L2 of the next e-iteration's
// 26 stream addresses keeps the DRAM queue full across the FMA phase
// (demand bursts were leaving HBM idle ~30%).

#define NN 2048
#define BB 16
#define DD 8
#define EC_MAX 28      // 74 chunks x 28 >= 2048
#define THREADS 512
#define OTILE 1024

__global__ void ds_zero_kernel(float* __restrict__ out, int n) {
    int i = blockIdx.x * blockDim.x + threadIdx.x;
    if (i < n) out[i] = 0.0f;
}

__device__ __forceinline__ void pf_l2(const void* p) {
    asm volatile("prefetch.global.L2 [%0];" :: "l"(p));
}

__global__ __launch_bounds__(THREADS, 1) void ds_main_kernel(
    const float* __restrict__ W,         // (N,N)
    const float* __restrict__ Wlong,     // (B,N,N)
    const float* __restrict__ Wshort,    // (D,B,N)
    const float* __restrict__ Xd,        // (D,B,N)
    const float* __restrict__ delaymap,  // (D,N,N)
    const float* __restrict__ frac,      // (N,N)
    const float* __restrict__ signs_pre, // (N,)
    float* __restrict__ out)             // (B,N)
{
    __shared__ float coef[EC_MAX][DD][BB]; // b fastest -> LDS.128 broadcast
    __shared__ float sgn_sh[EC_MAX];

    const int tid  = threadIdx.x;
    const int o    = blockIdx.x * OTILE + tid * 2;
    const int e0   = blockIdx.y * EC_MAX;
    const int eend = min(e0 + EC_MAX, NN);
    const int ecnt = eend - e0;

    // Cooperative coef preload (coalesced in e, guarded tail).
    for (int idx = tid; idx < DD * BB * EC_MAX; idx += THREADS) {
        int el   = idx % EC_MAX;
        int rest = idx / EC_MAX;
        int b    = rest % BB;
        int d    = rest / BB;
        if (el < ecnt) {
            int gi = (d * BB + b) * NN + (e0 + el);
            coef[el][d][b] = Xd[gi] * (Wshort[gi] + 1.0f);
        }
    }
    if (tid < ecnt) {
        float sp = signs_pre[e0 + tid];
        sgn_sh[tid] = (sp > 0.0f) ? 1.0f : ((sp < 0.0f) ? -1.0f : 0.0f);
    }
    __syncthreads();

    float2 acc[BB];
#pragma unroll
    for (int b = 0; b < BB; b++) acc[b] = make_float2(0.f, 0.f);

    for (int el = 0; el < ecnt; el++) {
        const int e = e0 + el;
        const long base_eo = (long)e * NN + o;

        // Register-free lookahead: pull e+1 lines toward L2 while computing e.
        {
            const int en = (e + 1 < NN) ? (e + 1) : e;
            const long bn = (long)en * NN + o;
            pf_l2(W + bn);
            pf_l2(frac + bn);
#pragma unroll
            for (int d = 0; d < DD; d++)
                pf_l2(delaymap + (long)d * NN * NN + bn);
#pragma unroll
            for (int b = 0; b < BB; b++)
                pf_l2(Wlong + (long)b * NN * NN + bn);
        }

        const float2 w2 = __ldcs((const float2*)(W + base_eo));
        const float2 f2 = __ldcs((const float2*)(frac + base_eo));
        const float se = sgn_sh[el];

        const float sgx = (w2.x > 0.0f) ? se : 0.0f;
        const float sgy = (w2.y > 0.0f) ? se : 0.0f;
        float2 cbase, fs;
        cbase.x = sgx * w2.x * (1.0f - f2.x);  fs.x = sgx * f2.x;
        cbase.y = sgy * w2.y * (1.0f - f2.y);  fs.y = sgy * f2.y;

        float2 dm[DD];
#pragma unroll
        for (int d = 0; d < DD; d++)
            dm[d] = __ldcs((const float2*)(delaymap + (long)d * NN * NN + base_eo));

        const float4* cel = (const float4*)coef[el];

#pragma unroll
        for (int g = 0; g < BB / 4; g++) {
            float2 p0 = make_float2(0.f, 0.f), p1 = p0, p2 = p0, p3 = p0;
#pragma unroll
            for (int d = 0; d < DD; d++) {
                const float4 c = cel[d * (BB / 4) + g];   // LDS.128 broadcast
                p0.x = fmaf(dm[d].x, c.x, p0.x);  p0.y = fmaf(dm[d].y, c.x, p0.y);
                p1.x = fmaf(dm[d].x, c.y, p1.x);  p1.y = fmaf(dm[d].y, c.y, p1.y);
                p2.x = fmaf(dm[d].x, c.z, p2.x);  p2.y = fmaf(dm[d].y, c.z, p2.y);
                p3.x = fmaf(dm[d].x, c.w, p3.x);  p3.y = fmaf(dm[d].y, c.w, p3.y);
            }
            const int b0 = 4 * g;
            const float2 wl0 = __ldcs((const float2*)(Wlong + (long)(b0 + 0) * NN * NN + base_eo));
            const float2 wl1 = __ldcs((const float2*)(Wlong + (long)(b0 + 1) * NN * NN + base_eo));
            const float2 wl2 = __ldcs((const float2*)(Wlong + (long)(b0 + 2) * NN * NN + base_eo));
            const float2 wl3 = __ldcs((const float2*)(Wlong + (long)(b0 + 3) * NN * NN + base_eo));

            acc[b0 + 0].x = fmaf(fmaf(fs.x, wl0.x, cbase.x), p0.x, acc[b0 + 0].x);
            acc[b0 + 0].y = fmaf(fmaf(fs.y, wl0.y, cbase.y), p0.y, acc[b0 + 0].y);
            acc[b0 + 1].x = fmaf(fmaf(fs.x, wl1.x, cbase.x), p1.x, acc[b0 + 1].x);
            acc[b0 + 1].y = fmaf(fmaf(fs.y, wl1.y, cbase.y), p1.y, acc[b0 + 1].y);
            acc[b0 + 2].x = fmaf(fmaf(fs.x, wl2.x, cbase.x), p2.x, acc[b0 + 2].x);
            acc[b0 + 2].y = fmaf(fmaf(fs.y, wl2.y, cbase.y), p2.y, acc[b0 + 2].y);
            acc[b0 + 3].x = fmaf(fmaf(fs.x, wl3.x, cbase.x), p3.x, acc[b0 + 3].x);
            acc[b0 + 3].y = fmaf(fmaf(fs.y, wl3.y, cbase.y), p3.y, acc[b0 + 3].y);
        }
    }

#pragma unroll
    for (int b = 0; b < BB; b++) {
        atomicAdd(&out[b * NN + o + 0], acc[b].x);
        atomicAdd(&out[b * NN + o + 1], acc[b].y);
    }
}

extern "C" void kernel_launch(void* const* d_in, const int* in_sizes, int n_in,
                              void* d_out, int out_size) {
    const float* W         = (const float*)d_in[0];
    const float* Wlong     = (const float*)d_in[1];
    const float* Wshort    = (const float*)d_in[2];
    const float* Xd        = (const float*)d_in[3];
    const float* delaymap  = (const float*)d_in[4];
    const float* STDP_frac = (const float*)d_in[5];
    const float* signs_pre = (const float*)d_in[6];
    float* out = (float*)d_out;

    ds_zero_kernel<<<(BB * NN + 255) / 256, 256>>>(out, BB * NN);

    dim3 grid(NN / OTILE, (NN + EC_MAX - 1) / EC_MAX); // (2, 74) = 148 CTAs
    ds_main_kernel<<<grid, THREADS>>>(W, Wlong, Wshort, Xd, delaymap,
                                      STDP_frac, signs_pre, out);
}